// round 1
// baseline (speedup 1.0000x reference)
#include <cuda_runtime.h>

#define BSZ 2
#define TLEN 2048
#define NH 16
#define PP 64
#define NN 64

// One warp per (b, h, p). Lane L owns states n=L and n=L+32.
// Per step: h[n] = dA*h[n] + (dt*x)*B[n];  y = warp-reduce(h[n]*C[n]).
__global__ __launch_bounds__(256, 8) void ssd_scan_kernel(
    const float* __restrict__ X,      // [B,T,H,P]
    const float* __restrict__ delta,  // [B,T,H]
    const float* __restrict__ Bm,     // [B,T,N]
    const float* __restrict__ Cm,     // [B,T,N]
    const float* __restrict__ A_log,  // [H]
    float* __restrict__ y,            // [B,T,H,P]
    float* __restrict__ hlast)        // [B,H,P,N]
{
    const int warpId = (blockIdx.x * blockDim.x + threadIdx.x) >> 5;
    const int lane = threadIdx.x & 31;
    if (warpId >= BSZ * NH * PP) return;

    const int b  = warpId / (NH * PP);
    const int rem = warpId % (NH * PP);
    const int hh = rem / PP;
    const int p  = rem % PP;

    const float negA = -__expf(A_log[hh]);

    const float* Xp = X     + ((size_t)((size_t)b * TLEN) * NH + hh) * PP + p;
    const float* dp = delta + ((size_t)b * TLEN) * NH + hh;
    const float* Bp = Bm    + ((size_t)b * TLEN) * NN;
    const float* Cp = Cm    + ((size_t)b * TLEN) * NN;
    float*       yp = y     + ((size_t)((size_t)b * TLEN) * NH + hh) * PP + p;

    const int n0 = lane;
    const int n1 = lane + 32;

    float h0 = 0.0f, h1 = 0.0f;

    #pragma unroll 4
    for (int t = 0; t < TLEN; ++t) {
        const float dt = __ldg(dp);
        const float dA = __expf(dt * negA);
        const float s  = dt * __ldg(Xp);
        const float b0 = __ldg(Bp + n0);
        const float b1 = __ldg(Bp + n1);
        const float c0 = __ldg(Cp + n0);
        const float c1 = __ldg(Cp + n1);

        h0 = fmaf(dA, h0, s * b0);
        h1 = fmaf(dA, h1, s * b1);

        float yv = fmaf(h0, c0, h1 * c1);
        #pragma unroll
        for (int o = 16; o; o >>= 1)
            yv += __shfl_xor_sync(0xffffffffu, yv, o);
        if (lane == 0) *yp = yv;

        Xp += NH * PP;
        dp += NH;
        Bp += NN;
        Cp += NN;
        yp += NH * PP;
    }

    // Final state: [B,H,P,N]
    float* hp = hlast + ((size_t)((b * NH + hh) * PP + p)) * NN;
    hp[n0] = h0;
    hp[n1] = h1;
}

extern "C" void kernel_launch(void* const* d_in, const int* in_sizes, int n_in,
                              void* d_out, int out_size) {
    const float* X     = (const float*)d_in[0];
    const float* delta = (const float*)d_in[1];
    const float* Bm    = (const float*)d_in[2];
    const float* Cm    = (const float*)d_in[3];
    const float* A_log = (const float*)d_in[4];

    float* y     = (float*)d_out;
    float* hlast = y + (size_t)BSZ * TLEN * NH * PP;

    const int totalWarps = BSZ * NH * PP;          // 2048
    const int threads = 256;                       // 8 warps/block
    const int blocks = (totalWarps * 32 + threads - 1) / threads;  // 256
    ssd_scan_kernel<<<blocks, threads>>>(X, delta, Bm, Cm, A_log, y, hlast);
}

// round 2
// speedup vs baseline: 3.2533x; 3.2533x over previous
#include <cuda_runtime.h>

#define BSZ 2
#define TLEN 2048
#define NH 16
#define PP 64
#define NN 64
#define CHL 64                 // chunk length
#define NCH (TLEN / CHL)       // 32 chunks

// Scratch (device globals; allocation-free).
__device__ float g_S [BSZ * NH * NCH * PP * NN];  // per-chunk local final state
__device__ float g_H0[BSZ * NH * NCH * PP * NN];  // state entering each chunk
__device__ float g_A [BSZ * NH * NCH];            // per-chunk total decay

// ---------------------------------------------------------------------------
// K1: intra-chunk scan. One warp per (b,h,chunk,p-group-of-4).
// Lane layout: lane = p_sub*8 + n_grp; lane owns p = pg*4+p_sub, n = n_grp*8..+7.
// Per step: h[k] = dA*h[k] + (dt*x)*B[k]; y_intra = reduce over 8 lanes (3 shfl).
// ---------------------------------------------------------------------------
__global__ __launch_bounds__(256) void k1_intra(
    const float* __restrict__ X,      // [B,T,H,P]
    const float* __restrict__ delta,  // [B,T,H]
    const float* __restrict__ Bm,     // [B,T,N]
    const float* __restrict__ Cm,     // [B,T,N]
    const float* __restrict__ A_log,  // [H]
    float* __restrict__ y)            // [B,T,H,P]
{
    const int w    = (blockIdx.x * blockDim.x + threadIdx.x) >> 5;
    const int lane = threadIdx.x & 31;
    const int pg = w & 15;
    const int c  = (w >> 4) & (NCH - 1);
    const int hh = (w >> 9) & 15;
    const int b  = w >> 13;

    const int p_sub = lane >> 3;
    const int n_grp = lane & 7;
    const int p = pg * 4 + p_sub;

    const float negA = -__expf(A_log[hh]);
    const int t0 = c * CHL;

    const float*  dp = delta + ((size_t)b * TLEN + t0) * NH + hh;
    const float*  Xp = X + (((size_t)b * TLEN + t0) * NH + hh) * PP + p;
    const float4* Bp = (const float4*)(Bm + ((size_t)b * TLEN + t0) * NN) + n_grp * 2;
    const float4* Cp = (const float4*)(Cm + ((size_t)b * TLEN + t0) * NN) + n_grp * 2;
    float*        yp = y + (((size_t)b * TLEN + t0) * NH + hh) * PP + p;

    float h0=0.f,h1=0.f,h2=0.f,h3=0.f,h4=0.f,h5=0.f,h6=0.f,h7=0.f;
    float a = 1.0f;

    #pragma unroll 4
    for (int t = 0; t < CHL; ++t) {
        const float  dt = __ldg(dp);
        const float  dA = __expf(dt * negA);
        const float  s  = dt * __ldg(Xp);
        const float4 bv0 = __ldg(Bp);
        const float4 bv1 = __ldg(Bp + 1);
        const float4 cv0 = __ldg(Cp);
        const float4 cv1 = __ldg(Cp + 1);

        h0 = fmaf(dA, h0, s * bv0.x);
        h1 = fmaf(dA, h1, s * bv0.y);
        h2 = fmaf(dA, h2, s * bv0.z);
        h3 = fmaf(dA, h3, s * bv0.w);
        h4 = fmaf(dA, h4, s * bv1.x);
        h5 = fmaf(dA, h5, s * bv1.y);
        h6 = fmaf(dA, h6, s * bv1.z);
        h7 = fmaf(dA, h7, s * bv1.w);

        float yv = h0 * cv0.x;
        yv = fmaf(h1, cv0.y, yv);
        yv = fmaf(h2, cv0.z, yv);
        yv = fmaf(h3, cv0.w, yv);
        yv = fmaf(h4, cv1.x, yv);
        yv = fmaf(h5, cv1.y, yv);
        yv = fmaf(h6, cv1.z, yv);
        yv = fmaf(h7, cv1.w, yv);

        yv += __shfl_xor_sync(0xffffffffu, yv, 1);
        yv += __shfl_xor_sync(0xffffffffu, yv, 2);
        yv += __shfl_xor_sync(0xffffffffu, yv, 4);
        if (n_grp == 0) *yp = yv;

        a *= dA;
        dp += NH; Xp += NH * PP; Bp += NN / 4; Cp += NN / 4; yp += NH * PP;
    }

    // Store per-chunk local state S[b][h][c][p][n]
    float* Sp = g_S + ((((size_t)(b * NH + hh) * NCH + c) * PP + p) * NN) + n_grp * 8;
    *(float4*)Sp       = make_float4(h0, h1, h2, h3);
    *(float4*)(Sp + 4) = make_float4(h4, h5, h6, h7);
    if (lane == 0 && pg == 0) g_A[(b * NH + hh) * NCH + c] = a;
}

// ---------------------------------------------------------------------------
// K2: scan across chunks. One warp per (b,h,p); lane owns n=lane, n=lane+32.
// H0[0]=0; H0[c] = A_{c-1} H0[c-1] + S_{c-1}; also emits h_last.
// ---------------------------------------------------------------------------
__global__ __launch_bounds__(256) void k2_scan(float* __restrict__ hlast) // [B,H,P,N]
{
    const int w    = (blockIdx.x * blockDim.x + threadIdx.x) >> 5;  // (b*NH+h)*PP + p
    const int lane = threadIdx.x & 31;
    const int bh = w / PP;         // b*NH + h
    const int p  = w % PP;

    float h0 = 0.f, h1 = 0.f;
    for (int c = 0; c < NCH; ++c) {
        const size_t off = (((size_t)bh * NCH + c) * PP + p) * NN;
        g_H0[off + lane]      = h0;
        g_H0[off + lane + 32] = h1;
        const float A = g_A[bh * NCH + c];
        h0 = fmaf(A, h0, g_S[off + lane]);
        h1 = fmaf(A, h1, g_S[off + lane + 32]);
    }
    float* hp = hlast + (size_t)w * NN;
    hp[lane]      = h0;
    hp[lane + 32] = h1;
}

// ---------------------------------------------------------------------------
// K3: inter-chunk correction. One block per (b,h,c):
//   y[t,p] += a_t * sum_n C[t,n] * H0[p,n],  a_t = exp(negA * cumsum(delta))
// 256 threads, each computes a 4t x 4p register tile over smem tiles.
// ---------------------------------------------------------------------------
__global__ __launch_bounds__(256) void k3_corr(
    const float* __restrict__ delta,
    const float* __restrict__ Cm,
    const float* __restrict__ A_log,
    float* __restrict__ y)
{
    const int blk = blockIdx.x;            // (b*NH+h)*NCH + c
    const int c  = blk % NCH;
    const int hh = (blk / NCH) % NH;
    const int b  = blk / (NCH * NH);
    const int t0 = c * CHL;
    const int tid = threadIdx.x;

    __shared__ float sh_h[PP][NN + 4];     // padded (stride 68)
    __shared__ float sh_C[CHL][NN + 4];
    __shared__ float sh_d[CHL];
    __shared__ float sh_a[CHL];

    // Stage H0 tile
    {
        const float* Hp = g_H0 + (((size_t)(b * NH + hh) * NCH + c) * PP) * NN;
        for (int i = tid; i < PP * NN / 4; i += 256) {
            const int r = i / (NN / 4), q = i % (NN / 4);
            float4 v = __ldg((const float4*)Hp + i);
            *(float4*)&sh_h[r][q * 4] = v;
        }
    }
    // Stage C tile
    {
        const float4* Cp = (const float4*)(Cm + ((size_t)b * TLEN + t0) * NN);
        for (int i = tid; i < CHL * NN / 4; i += 256) {
            const int r = i / (NN / 4), q = i % (NN / 4);
            *(float4*)&sh_C[r][q * 4] = __ldg(Cp + i);
        }
    }
    if (tid < CHL)
        sh_d[tid] = __ldg(delta + ((size_t)b * TLEN + t0 + tid) * NH + hh);
    __syncthreads();

    // Inclusive Kogge-Stone cumsum of delta over the chunk
    for (int off = 1; off < CHL; off <<= 1) {
        float v = 0.f;
        if (tid < CHL && tid >= off) v = sh_d[tid - off];
        __syncthreads();
        if (tid < CHL) sh_d[tid] += v;
        __syncthreads();
    }
    if (tid < CHL) {
        const float negA = -__expf(A_log[hh]);
        sh_a[tid] = __expf(negA * sh_d[tid]);
    }
    __syncthreads();

    // Compute tile: thread (i = tid%16, j = tid/16): p = i + pi*16, t = j + tj*16
    const int i = tid & 15;
    const int j = tid >> 4;

    float acc[4][4];
    #pragma unroll
    for (int a0 = 0; a0 < 4; ++a0)
        #pragma unroll
        for (int a1 = 0; a1 < 4; ++a1) acc[a0][a1] = 0.f;

    #pragma unroll 4
    for (int n4 = 0; n4 < NN / 4; ++n4) {
        float4 hv[4], cv[4];
        #pragma unroll
        for (int pi = 0; pi < 4; ++pi) hv[pi] = *(const float4*)&sh_h[i + pi * 16][n4 * 4];
        #pragma unroll
        for (int tj = 0; tj < 4; ++tj) cv[tj] = *(const float4*)&sh_C[j + tj * 16][n4 * 4];
        #pragma unroll
        for (int tj = 0; tj < 4; ++tj)
            #pragma unroll
            for (int pi = 0; pi < 4; ++pi) {
                acc[tj][pi] = fmaf(cv[tj].x, hv[pi].x, acc[tj][pi]);
                acc[tj][pi] = fmaf(cv[tj].y, hv[pi].y, acc[tj][pi]);
                acc[tj][pi] = fmaf(cv[tj].z, hv[pi].z, acc[tj][pi]);
                acc[tj][pi] = fmaf(cv[tj].w, hv[pi].w, acc[tj][pi]);
            }
    }

    // y += a_t * acc
    #pragma unroll
    for (int tj = 0; tj < 4; ++tj) {
        const int t = j + tj * 16;
        const float at = sh_a[t];
        float* yrow = y + (((size_t)b * TLEN + t0 + t) * NH + hh) * PP;
        #pragma unroll
        for (int pi = 0; pi < 4; ++pi) {
            const int p = i + pi * 16;
            yrow[p] = fmaf(at, acc[tj][pi], yrow[p]);
        }
    }
}

extern "C" void kernel_launch(void* const* d_in, const int* in_sizes, int n_in,
                              void* d_out, int out_size) {
    const float* X     = (const float*)d_in[0];
    const float* delta = (const float*)d_in[1];
    const float* Bm    = (const float*)d_in[2];
    const float* Cm    = (const float*)d_in[3];
    const float* A_log = (const float*)d_in[4];

    float* y     = (float*)d_out;
    float* hlast = y + (size_t)BSZ * TLEN * NH * PP;

    // K1: B*H*NCH*(P/4) warps = 16384 -> 2048 blocks x 256
    k1_intra<<<2048, 256>>>(X, delta, Bm, Cm, A_log, y);
    // K2: B*H*P warps = 2048 -> 256 blocks x 256
    k2_scan<<<256, 256>>>(hlast);
    // K3: one block per (b,h,c) = 1024
    k3_corr<<<1024, 256>>>(delta, Cm, A_log, y);
}

// round 7
// speedup vs baseline: 7.8256x; 2.4054x over previous
#include <cuda_runtime.h>

#define BSZ 2
#define TLEN 2048
#define NH 16
#define PP 64
#define NN 64
#define CHL 64                 // chunk length
#define NCH (TLEN / CHL)       // 32 chunks
#define LDS_ (NN + 4)          // padded row stride (68)
#define IDX(r,c) ((r) * LDS_ + (c))

// Scratch (device globals; allocation-free).
__device__ float g_S  [BSZ * NH * NCH * PP * NN];  // per-chunk local final state [bh][c][p][n]
__device__ float g_H0 [BSZ * NH * NCH * PP * NN];  // state entering each chunk   [bh][c][p][n]
__device__ float g_A  [BSZ * NH * NCH];            // per-chunk total decay
__device__ float g_a  [BSZ * NH * NCH * CHL];      // a_t = exp(negA*cum_t)
__device__ float g_cum[BSZ * NH * NCH * CHL];      // inclusive cumsum of delta

// ---------------------------------------------------------------------------
// K1: per-chunk state S[p][n] = sum_s r_s * B[s,n] * X[s,p],
//     r_s = exp(negA*(cumTot - cum_s)) * delta_s.  Also emits a_t, cum_t, A_c.
// One block per (b,h,c). 256 threads, 4x4 register tile.
// ---------------------------------------------------------------------------
__global__ __launch_bounds__(256) void k1_state(
    const float* __restrict__ X,      // [B,T,H,P]
    const float* __restrict__ delta,  // [B,T,H]
    const float* __restrict__ Bm,     // [B,T,N]
    const float* __restrict__ A_log)  // [H]
{
    const int blk = blockIdx.x;            // (b*NH+h)*NCH + c
    const int c  = blk % NCH;
    const int hh = (blk / NCH) % NH;
    const int b  = blk / (NCH * NH);
    const int t0 = c * CHL;
    const int tid = threadIdx.x;

    __shared__ float sB[CHL * LDS_];
    __shared__ float sX[CHL * LDS_];
    __shared__ float sh_d[CHL], sh_cum[CHL], sh_r[CHL];

    const float negA = -__expf(A_log[hh]);

    // Stage delta and X
    if (tid < CHL) {
        float d = __ldg(delta + ((size_t)b * TLEN + t0 + tid) * NH + hh);
        sh_d[tid] = d;
        sh_cum[tid] = d;
    }
    for (int i = tid; i < CHL * PP / 4; i += 256) {
        const int r = i >> 4, q = i & 15;
        const float4 v = __ldg((const float4*)(X + (((size_t)b * TLEN + t0 + r) * NH + hh) * PP) + q);
        *(float4*)&sX[IDX(r, q * 4)] = v;
    }
    __syncthreads();

    // Inclusive Kogge-Stone cumsum over 64
    for (int off = 1; off < CHL; off <<= 1) {
        float v = 0.f;
        if (tid < CHL && tid >= off) v = sh_cum[tid - off];
        __syncthreads();
        if (tid < CHL) sh_cum[tid] += v;
        __syncthreads();
    }
    const float cumTot = sh_cum[CHL - 1];
    if (tid < CHL) {
        const float cum = sh_cum[tid];
        g_a  [(size_t)blk * CHL + tid] = __expf(negA * cum);
        g_cum[(size_t)blk * CHL + tid] = cum;
        sh_r[tid] = __expf(negA * (cumTot - cum)) * sh_d[tid];
    }
    if (tid == 0) g_A[blk] = __expf(negA * cumTot);
    __syncthreads();

    // Stage B scaled by r_s
    for (int i = tid; i < CHL * NN / 4; i += 256) {
        const int r = i >> 4, q = i & 15;
        float4 v = __ldg((const float4*)(Bm + ((size_t)b * TLEN + t0 + r) * NN) + q);
        const float rr = sh_r[r];
        v.x *= rr; v.y *= rr; v.z *= rr; v.w *= rr;
        *(float4*)&sB[IDX(r, q * 4)] = v;
    }
    __syncthreads();

    // GEMM: S[p][n] = sum_s sB[s][n] * sX[s][p].  i -> n (coalesced), j -> p.
    const int i = tid & 15;
    const int j = tid >> 4;
    float acc[4][4];
    #pragma unroll
    for (int a0 = 0; a0 < 4; ++a0)
        #pragma unroll
        for (int a1 = 0; a1 < 4; ++a1) acc[a0][a1] = 0.f;

    #pragma unroll 4
    for (int s = 0; s < CHL; ++s) {
        float bv[4], xv[4];
        #pragma unroll
        for (int ni = 0; ni < 4; ++ni) bv[ni] = sB[IDX(s, i + 16 * ni)];
        #pragma unroll
        for (int pj = 0; pj < 4; ++pj) xv[pj] = sX[IDX(s, j + 16 * pj)];
        #pragma unroll
        for (int pj = 0; pj < 4; ++pj)
            #pragma unroll
            for (int ni = 0; ni < 4; ++ni)
                acc[pj][ni] = fmaf(bv[ni], xv[pj], acc[pj][ni]);
    }

    float* Sp = g_S + (size_t)blk * PP * NN;
    #pragma unroll
    for (int pj = 0; pj < 4; ++pj) {
        const int p = j + 16 * pj;
        #pragma unroll
        for (int ni = 0; ni < 4; ++ni)
            Sp[p * NN + i + 16 * ni] = acc[pj][ni];
    }
}

// ---------------------------------------------------------------------------
// K2: cross-chunk scan, one thread per (bh, p, n). Fully unrolled over 32 chunks.
// ---------------------------------------------------------------------------
__global__ __launch_bounds__(256) void k2_scan(float* __restrict__ hlast) // [B,H,P,N]
{
    const int idx = blockIdx.x * 256 + threadIdx.x;   // bh*PP*NN + p*NN + n
    const int bh = idx >> 12;
    const int pn = idx & 4095;

    float h = 0.f;
    #pragma unroll
    for (int c = 0; c < NCH; ++c) {
        const size_t off = ((size_t)bh * NCH + c) * (PP * NN) + pn;
        g_H0[off] = h;
        h = fmaf(g_A[bh * NCH + c], h, g_S[off]);
    }
    hlast[(size_t)bh * PP * NN + pn] = h;
}

// ---------------------------------------------------------------------------
// K3: per-chunk output.
//   G[t,s] = sum_n C[t,n]B[s,n]
//   W[t,s] = (s<=t) ? exp(negA*(cum_t-cum_s)) * delta_s * G[t,s] : 0
//   Y[t,p] = sum_s W[t,s] X[s,p]  +  a_t * sum_n C[t,n] H0[p,n]
// One block per (b,h,c). Dynamic smem: sB(->W), sC, sX, sH.
// ---------------------------------------------------------------------------
__global__ __launch_bounds__(256) void k3_out(
    const float* __restrict__ X,
    const float* __restrict__ delta,
    const float* __restrict__ Bm,
    const float* __restrict__ Cm,
    const float* __restrict__ A_log,
    float* __restrict__ y)
{
    extern __shared__ float smem[];
    float* sB = smem;                    // [CHL][LDS_]  (aliased as sW later)
    float* sC = sB + CHL * LDS_;
    float* sX = sC + CHL * LDS_;
    float* sH = sX + CHL * LDS_;
    float* sW = sB;

    __shared__ float sh_d[CHL], sh_cum[CHL], sh_a[CHL];

    const int blk = blockIdx.x;
    const int c  = blk % NCH;
    const int hh = (blk / NCH) % NH;
    const int b  = blk / (NCH * NH);
    const int t0 = c * CHL;
    const int tid = threadIdx.x;

    const float negA = -__expf(A_log[hh]);

    if (tid < CHL) {
        sh_d[tid]   = __ldg(delta + ((size_t)b * TLEN + t0 + tid) * NH + hh);
        sh_cum[tid] = g_cum[(size_t)blk * CHL + tid];
        sh_a[tid]   = g_a  [(size_t)blk * CHL + tid];
    }
    for (int i = tid; i < CHL * NN / 4; i += 256) {
        const int r = i >> 4, q = i & 15;
        *(float4*)&sB[IDX(r, q * 4)] =
            __ldg((const float4*)(Bm + ((size_t)b * TLEN + t0 + r) * NN) + q);
        *(float4*)&sC[IDX(r, q * 4)] =
            __ldg((const float4*)(Cm + ((size_t)b * TLEN + t0 + r) * NN) + q);
    }
    for (int i = tid; i < CHL * PP / 4; i += 256) {
        const int r = i >> 4, q = i & 15;
        *(float4*)&sX[IDX(r, q * 4)] =
            __ldg((const float4*)(X + (((size_t)b * TLEN + t0 + r) * NH + hh) * PP) + q);
    }
    {
        const float* Hp = g_H0 + (size_t)blk * PP * NN;
        for (int i = tid; i < PP * NN / 4; i += 256) {
            const int r = i >> 4, q = i & 15;
            *(float4*)&sH[IDX(r, q * 4)] = __ldg((const float4*)Hp + i);
        }
    }
    __syncthreads();

    const int i = tid & 15;    // -> s (GEMM1) / p (GEMM2)
    const int j = tid >> 4;    // -> t

    // GEMM1: G[t,s], t = j+16tj, s = i+16si, reduce over n (float4)
    float g[4][4];
    #pragma unroll
    for (int a0 = 0; a0 < 4; ++a0)
        #pragma unroll
        for (int a1 = 0; a1 < 4; ++a1) g[a0][a1] = 0.f;

    #pragma unroll 4
    for (int n4 = 0; n4 < NN / 4; ++n4) {
        float4 cv[4], bv[4];
        #pragma unroll
        for (int tj = 0; tj < 4; ++tj) cv[tj] = *(const float4*)&sC[IDX(j + 16 * tj, n4 * 4)];
        #pragma unroll
        for (int si = 0; si < 4; ++si) bv[si] = *(const float4*)&sB[IDX(i + 16 * si, n4 * 4)];
        #pragma unroll
        for (int tj = 0; tj < 4; ++tj)
            #pragma unroll
            for (int si = 0; si < 4; ++si) {
                g[tj][si] = fmaf(cv[tj].x, bv[si].x, g[tj][si]);
                g[tj][si] = fmaf(cv[tj].y, bv[si].y, g[tj][si]);
                g[tj][si] = fmaf(cv[tj].z, bv[si].z, g[tj][si]);
                g[tj][si] = fmaf(cv[tj].w, bv[si].w, g[tj][si]);
            }
    }
    __syncthreads();   // all GEMM1 reads of sB done before sW overwrites it

    // W = mask * exp * delta * G
    #pragma unroll
    for (int tj = 0; tj < 4; ++tj) {
        const int t = j + 16 * tj;
        const float ct = sh_cum[t];
        #pragma unroll
        for (int si = 0; si < 4; ++si) {
            const int s = i + 16 * si;
            const float arg = negA * (ct - sh_cum[s]);
            const float e = __expf(fminf(arg, 0.f));
            sW[IDX(t, s)] = (s <= t) ? e * sh_d[s] * g[tj][si] : 0.f;
        }
    }
    __syncthreads();

    // GEMM2: Y[t,p] = sum_s W[t,s] X[s,p]   (+ a_t * sum_n C[t,n] H0[p,n])
    float acc[4][4], acc2[4][4];
    #pragma unroll
    for (int a0 = 0; a0 < 4; ++a0)
        #pragma unroll
        for (int a1 = 0; a1 < 4; ++a1) { acc[a0][a1] = 0.f; acc2[a0][a1] = 0.f; }

    #pragma unroll 2
    for (int s = 0; s < CHL; ++s) {
        float wv[4], xv[4];
        #pragma unroll
        for (int tj = 0; tj < 4; ++tj) wv[tj] = sW[IDX(j + 16 * tj, s)];
        #pragma unroll
        for (int pi = 0; pi < 4; ++pi) xv[pi] = sX[IDX(s, i + 16 * pi)];
        #pragma unroll
        for (int tj = 0; tj < 4; ++tj)
            #pragma unroll
            for (int pi = 0; pi < 4; ++pi)
                acc[tj][pi] = fmaf(wv[tj], xv[pi], acc[tj][pi]);
    }

    #pragma unroll 4
    for (int n4 = 0; n4 < NN / 4; ++n4) {
        float4 cv[4], hv[4];
        #pragma unroll
        for (int tj = 0; tj < 4; ++tj) cv[tj] = *(const float4*)&sC[IDX(j + 16 * tj, n4 * 4)];
        #pragma unroll
        for (int pi = 0; pi < 4; ++pi) hv[pi] = *(const float4*)&sH[IDX(i + 16 * pi, n4 * 4)];
        #pragma unroll
        for (int tj = 0; tj < 4; ++tj)
            #pragma unroll
            for (int pi = 0; pi < 4; ++pi) {
                acc2[tj][pi] = fmaf(cv[tj].x, hv[pi].x, acc2[tj][pi]);
                acc2[tj][pi] = fmaf(cv[tj].y, hv[pi].y, acc2[tj][pi]);
                acc2[tj][pi] = fmaf(cv[tj].z, hv[pi].z, acc2[tj][pi]);
                acc2[tj][pi] = fmaf(cv[tj].w, hv[pi].w, acc2[tj][pi]);
            }
    }

    // Store y (single write, coalesced over p)
    #pragma unroll
    for (int tj = 0; tj < 4; ++tj) {
        const int t = j + 16 * tj;
        const float at = sh_a[t];
        float* yrow = y + (((size_t)b * TLEN + t0 + t) * NH + hh) * PP;
        #pragma unroll
        for (int pi = 0; pi < 4; ++pi)
            yrow[i + 16 * pi] = fmaf(at, acc2[tj][pi], acc[tj][pi]);
    }
}

extern "C" void kernel_launch(void* const* d_in, const int* in_sizes, int n_in,
                              void* d_out, int out_size) {
    const float* X     = (const float*)d_in[0];
    const float* delta = (const float*)d_in[1];
    const float* Bm    = (const float*)d_in[2];
    const float* Cm    = (const float*)d_in[3];
    const float* A_log = (const float*)d_in[4];

    float* y     = (float*)d_out;
    float* hlast = y + (size_t)BSZ * TLEN * NH * PP;

    const int k3_smem = 4 * CHL * LDS_ * (int)sizeof(float);  // 69632 B
    cudaFuncSetAttribute(k3_out, cudaFuncAttributeMaxDynamicSharedMemorySize, k3_smem);

    k1_state<<<BSZ * NH * NCH, 256>>>(X, delta, Bm, A_log);          // 1024 blocks
    k2_scan<<<(BSZ * NH * PP * NN) / 256, 256>>>(hlast);             // 512 blocks
    k3_out<<<BSZ * NH * NCH, 256, k3_smem>>>(X, delta, Bm, Cm, A_log, y);
}

// round 9
// speedup vs baseline: 8.4698x; 1.0823x over previous
#include <cuda_runtime.h>

#define BSZ 2
#define TLEN 2048
#define NH 16
#define PP 64
#define NN 64
#define CHL 64                 // chunk length
#define NCH (TLEN / CHL)       // 32 chunks
#define LDS_ (NN + 4)          // padded row stride (68)
#define IDX(r,c) ((r) * LDS_ + (c))

// Scratch (device globals; allocation-free).
__device__ float g_S  [BSZ * NH * NCH * PP * NN];  // per-chunk local final state [bh][c][p][n]
__device__ float g_H0 [BSZ * NH * NCH * PP * NN];  // state entering each chunk   [bh][c][p][n]
__device__ float g_A  [BSZ * NH * NCH];            // per-chunk total decay
__device__ float g_a  [BSZ * NH * NCH * CHL];      // a_t = exp(negA*cum_t)
__device__ float g_cum[BSZ * NH * NCH * CHL];      // inclusive cumsum of delta

// ---------------------------------------------------------------------------
// K1: per-chunk state S[p][n] = sum_s r_s * B[s,n] * X[s,p],
//     r_s = exp(negA*(cumTot - cum_s)) * delta_s.  Also emits a_t, cum_t, A_c.
// One block per (b,h,c). 256 threads; 4x4 tile, CONSECUTIVE mapping, float4 LDS.
// ---------------------------------------------------------------------------
__global__ __launch_bounds__(256) void k1_state(
    const float* __restrict__ X,      // [B,T,H,P]
    const float* __restrict__ delta,  // [B,T,H]
    const float* __restrict__ Bm,     // [B,T,N]
    const float* __restrict__ A_log)  // [H]
{
    const int blk = blockIdx.x;            // (b*NH+h)*NCH + c
    const int c  = blk % NCH;
    const int hh = (blk / NCH) % NH;
    const int b  = blk / (NCH * NH);
    const int t0 = c * CHL;
    const int tid = threadIdx.x;

    __shared__ float sB[CHL * LDS_];
    __shared__ float sX[CHL * LDS_];
    __shared__ float sh_d[CHL], sh_cum[CHL], sh_r[CHL];

    const float negA = -__expf(A_log[hh]);

    // Stage delta and X
    if (tid < CHL) {
        float d = __ldg(delta + ((size_t)b * TLEN + t0 + tid) * NH + hh);
        sh_d[tid] = d;
        sh_cum[tid] = d;
    }
    for (int i = tid; i < CHL * PP / 4; i += 256) {
        const int r = i >> 4, q = i & 15;
        const float4 v = __ldg((const float4*)(X + (((size_t)b * TLEN + t0 + r) * NH + hh) * PP) + q);
        *(float4*)&sX[IDX(r, q * 4)] = v;
    }
    __syncthreads();

    // Inclusive Kogge-Stone cumsum over 64
    for (int off = 1; off < CHL; off <<= 1) {
        float v = 0.f;
        if (tid < CHL && tid >= off) v = sh_cum[tid - off];
        __syncthreads();
        if (tid < CHL) sh_cum[tid] += v;
        __syncthreads();
    }
    const float cumTot = sh_cum[CHL - 1];
    if (tid < CHL) {
        const float cum = sh_cum[tid];
        g_a  [(size_t)blk * CHL + tid] = __expf(negA * cum);
        g_cum[(size_t)blk * CHL + tid] = cum;
        sh_r[tid] = __expf(negA * (cumTot - cum)) * sh_d[tid];
    }
    if (tid == 0) g_A[blk] = __expf(negA * cumTot);
    __syncthreads();

    // Stage B scaled by r_s
    for (int i = tid; i < CHL * NN / 4; i += 256) {
        const int r = i >> 4, q = i & 15;
        float4 v = __ldg((const float4*)(Bm + ((size_t)b * TLEN + t0 + r) * NN) + q);
        const float rr = sh_r[r];
        v.x *= rr; v.y *= rr; v.z *= rr; v.w *= rr;
        *(float4*)&sB[IDX(r, q * 4)] = v;
    }
    __syncthreads();

    // GEMM: S[p][n] = sum_s sB[s][n] * sX[s][p].
    // Thread (i=tid&15, j=tid>>4): n = 4i..4i+3, p = 4j..4j+3. float4 reads.
    const int i = tid & 15;
    const int j = tid >> 4;
    float acc[4][4];   // [pj][ni]
    #pragma unroll
    for (int a0 = 0; a0 < 4; ++a0)
        #pragma unroll
        for (int a1 = 0; a1 < 4; ++a1) acc[a0][a1] = 0.f;

    #pragma unroll 8
    for (int s = 0; s < CHL; ++s) {
        const float4 bv = *(const float4*)&sB[IDX(s, 4 * i)];
        const float4 xv = *(const float4*)&sX[IDX(s, 4 * j)];
        acc[0][0] = fmaf(xv.x, bv.x, acc[0][0]);
        acc[0][1] = fmaf(xv.x, bv.y, acc[0][1]);
        acc[0][2] = fmaf(xv.x, bv.z, acc[0][2]);
        acc[0][3] = fmaf(xv.x, bv.w, acc[0][3]);
        acc[1][0] = fmaf(xv.y, bv.x, acc[1][0]);
        acc[1][1] = fmaf(xv.y, bv.y, acc[1][1]);
        acc[1][2] = fmaf(xv.y, bv.z, acc[1][2]);
        acc[1][3] = fmaf(xv.y, bv.w, acc[1][3]);
        acc[2][0] = fmaf(xv.z, bv.x, acc[2][0]);
        acc[2][1] = fmaf(xv.z, bv.y, acc[2][1]);
        acc[2][2] = fmaf(xv.z, bv.z, acc[2][2]);
        acc[2][3] = fmaf(xv.z, bv.w, acc[2][3]);
        acc[3][0] = fmaf(xv.w, bv.x, acc[3][0]);
        acc[3][1] = fmaf(xv.w, bv.y, acc[3][1]);
        acc[3][2] = fmaf(xv.w, bv.z, acc[3][2]);
        acc[3][3] = fmaf(xv.w, bv.w, acc[3][3]);
    }

    float* Sp = g_S + (size_t)blk * PP * NN;
    #pragma unroll
    for (int pj = 0; pj < 4; ++pj) {
        const int p = 4 * j + pj;
        *(float4*)(Sp + p * NN + 4 * i) =
            make_float4(acc[pj][0], acc[pj][1], acc[pj][2], acc[pj][3]);
    }
}

// ---------------------------------------------------------------------------
// K2: cross-chunk scan, one thread per (bh, p, n). Fully unrolled over 32 chunks.
// ---------------------------------------------------------------------------
__global__ __launch_bounds__(256) void k2_scan(float* __restrict__ hlast) // [B,H,P,N]
{
    const int idx = blockIdx.x * 256 + threadIdx.x;   // bh*PP*NN + p*NN + n
    const int bh = idx >> 12;
    const int pn = idx & 4095;

    float h = 0.f;
    #pragma unroll
    for (int c = 0; c < NCH; ++c) {
        const size_t off = ((size_t)bh * NCH + c) * (PP * NN) + pn;
        g_H0[off] = h;
        h = fmaf(g_A[bh * NCH + c], h, g_S[off]);
    }
    hlast[(size_t)bh * PP * NN + pn] = h;
}

// ---------------------------------------------------------------------------
// K3: per-chunk output.
//   G[t,s] = sum_n C[t,n]B[s,n]
//   W[t,s] = (s<=t) ? exp(negA*(cum_t-cum_s)) * delta_s * G[t,s] : 0
//   Y[t,p] = sum_s W[t,s] X[s,p]  +  a_t * sum_n C[t,n] H0[p,n]
// Phases: GEMM1 (strided tile) -> sWT[s][t] (aliases sB) + GEMM3 (strided tile)
//         -> sY2[t][p] = a_t*GEMM3 (aliases sH) -> GEMM2 (consecutive tile,
//         float4 both operands, triangular s-bound) + sY2 add -> STG.128.
// ---------------------------------------------------------------------------
__global__ __launch_bounds__(256) void k3_out(
    const float* __restrict__ X,
    const float* __restrict__ delta,
    const float* __restrict__ Bm,
    const float* __restrict__ Cm,
    const float* __restrict__ A_log,
    float* __restrict__ y)
{
    extern __shared__ float smem[];
    float* sB  = smem;                    // [CHL][LDS_]  -> later sWT[s][t]
    float* sC  = sB + CHL * LDS_;
    float* sX  = sC + CHL * LDS_;
    float* sH  = sX + CHL * LDS_;         // [PP][LDS_]   -> later sY2[t][p]
    float* sWT = sB;
    float* sY2 = sH;

    __shared__ float sh_d[CHL], sh_cum[CHL], sh_a[CHL];

    const int blk = blockIdx.x;
    const int c  = blk % NCH;
    const int hh = (blk / NCH) % NH;
    const int b  = blk / (NCH * NH);
    const int t0 = c * CHL;
    const int tid = threadIdx.x;

    const float negA = -__expf(A_log[hh]);

    if (tid < CHL) {
        sh_d[tid]   = __ldg(delta + ((size_t)b * TLEN + t0 + tid) * NH + hh);
        sh_cum[tid] = g_cum[(size_t)blk * CHL + tid];
        sh_a[tid]   = g_a  [(size_t)blk * CHL + tid];
    }
    for (int i = tid; i < CHL * NN / 4; i += 256) {
        const int r = i >> 4, q = i & 15;
        *(float4*)&sB[IDX(r, q * 4)] =
            __ldg((const float4*)(Bm + ((size_t)b * TLEN + t0 + r) * NN) + q);
        *(float4*)&sC[IDX(r, q * 4)] =
            __ldg((const float4*)(Cm + ((size_t)b * TLEN + t0 + r) * NN) + q);
    }
    for (int i = tid; i < CHL * PP / 4; i += 256) {
        const int r = i >> 4, q = i & 15;
        *(float4*)&sX[IDX(r, q * 4)] =
            __ldg((const float4*)(X + (((size_t)b * TLEN + t0 + r) * NH + hh) * PP) + q);
    }
    {
        const float* Hp = g_H0 + (size_t)blk * PP * NN;
        for (int i = tid; i < PP * NN / 4; i += 256) {
            const int r = i >> 4, q = i & 15;
            *(float4*)&sH[IDX(r, q * 4)] = __ldg((const float4*)Hp + i);
        }
    }
    __syncthreads();

    const int i = tid & 15;
    const int j = tid >> 4;

    // ---- GEMM1: G[t,s], t = j+16tj, s = i+16si, reduce over n (float4) ----
    float g[4][4];
    #pragma unroll
    for (int a0 = 0; a0 < 4; ++a0)
        #pragma unroll
        for (int a1 = 0; a1 < 4; ++a1) g[a0][a1] = 0.f;

    #pragma unroll 4
    for (int n4 = 0; n4 < NN / 4; ++n4) {
        float4 cv[4], bv[4];
        #pragma unroll
        for (int tj = 0; tj < 4; ++tj) cv[tj] = *(const float4*)&sC[IDX(j + 16 * tj, n4 * 4)];
        #pragma unroll
        for (int si = 0; si < 4; ++si) bv[si] = *(const float4*)&sB[IDX(i + 16 * si, n4 * 4)];
        #pragma unroll
        for (int tj = 0; tj < 4; ++tj)
            #pragma unroll
            for (int si = 0; si < 4; ++si) {
                g[tj][si] = fmaf(cv[tj].x, bv[si].x, g[tj][si]);
                g[tj][si] = fmaf(cv[tj].y, bv[si].y, g[tj][si]);
                g[tj][si] = fmaf(cv[tj].z, bv[si].z, g[tj][si]);
                g[tj][si] = fmaf(cv[tj].w, bv[si].w, g[tj][si]);
            }
    }
    __syncthreads();   // all GEMM1 reads of sB done before sWT overwrites it

    // ---- W transposed: sWT[s][t] = mask * exp * delta_s * G[t,s] ----
    #pragma unroll
    for (int tj = 0; tj < 4; ++tj) {
        const int t = j + 16 * tj;
        const float ct = sh_cum[t];
        #pragma unroll
        for (int si = 0; si < 4; ++si) {
            const int s = i + 16 * si;
            const float arg = negA * (ct - sh_cum[s]);
            const float e = __expf(fminf(arg, 0.f));
            sWT[IDX(s, t)] = (s <= t) ? e * sh_d[s] * g[tj][si] : 0.f;
        }
    }

    // ---- GEMM3: Y2[t,p] = sum_n C[t,n] H0[p,n], t = j+16tj, p = i+16pi ----
    float acc2[4][4];
    #pragma unroll
    for (int a0 = 0; a0 < 4; ++a0)
        #pragma unroll
        for (int a1 = 0; a1 < 4; ++a1) acc2[a0][a1] = 0.f;

    #pragma unroll 4
    for (int n4 = 0; n4 < NN / 4; ++n4) {
        float4 cv[4], hv[4];
        #pragma unroll
        for (int tj = 0; tj < 4; ++tj) cv[tj] = *(const float4*)&sC[IDX(j + 16 * tj, n4 * 4)];
        #pragma unroll
        for (int pi = 0; pi < 4; ++pi) hv[pi] = *(const float4*)&sH[IDX(i + 16 * pi, n4 * 4)];
        #pragma unroll
        for (int tj = 0; tj < 4; ++tj)
            #pragma unroll
            for (int pi = 0; pi < 4; ++pi) {
                acc2[tj][pi] = fmaf(cv[tj].x, hv[pi].x, acc2[tj][pi]);
                acc2[tj][pi] = fmaf(cv[tj].y, hv[pi].y, acc2[tj][pi]);
                acc2[tj][pi] = fmaf(cv[tj].z, hv[pi].z, acc2[tj][pi]);
                acc2[tj][pi] = fmaf(cv[tj].w, hv[pi].w, acc2[tj][pi]);
            }
    }
    __syncthreads();   // GEMM3 reads of sH done before sY2 overwrites it

    // ---- stage sY2[t][p] = a_t * Y2 ----
    #pragma unroll
    for (int tj = 0; tj < 4; ++tj) {
        const int t = j + 16 * tj;
        const float at = sh_a[t];
        #pragma unroll
        for (int pi = 0; pi < 4; ++pi)
            sY2[IDX(t, i + 16 * pi)] = at * acc2[tj][pi];
    }
    __syncthreads();

    // ---- GEMM2: Y[t,p] = sum_{s<=t} W[t,s] X[s,p], consecutive tiles ----
    // t = 4j..4j+3, p = 4i..4i+3. Warp-uniform triangular bound s < 8*(warp+1).
    const int sBound = ((tid >> 5) + 1) * 8;
    float acc[4][4];   // [tj][pi]
    #pragma unroll
    for (int a0 = 0; a0 < 4; ++a0)
        #pragma unroll
        for (int a1 = 0; a1 < 4; ++a1) acc[a0][a1] = 0.f;

    #pragma unroll 8
    for (int s = 0; s < sBound; ++s) {
        const float4 wv = *(const float4*)&sWT[IDX(s, 4 * j)];
        const float4 xv = *(const float4*)&sX[IDX(s, 4 * i)];
        acc[0][0] = fmaf(wv.x, xv.x, acc[0][0]);
        acc[0][1] = fmaf(wv.x, xv.y, acc[0][1]);
        acc[0][2] = fmaf(wv.x, xv.z, acc[0][2]);
        acc[0][3] = fmaf(wv.x, xv.w, acc[0][3]);
        acc[1][0] = fmaf(wv.y, xv.x, acc[1][0]);
        acc[1][1] = fmaf(wv.y, xv.y, acc[1][1]);
        acc[1][2] = fmaf(wv.y, xv.z, acc[1][2]);
        acc[1][3] = fmaf(wv.y, xv.w, acc[1][3]);
        acc[2][0] = fmaf(wv.z, xv.x, acc[2][0]);
        acc[2][1] = fmaf(wv.z, xv.y, acc[2][1]);
        acc[2][2] = fmaf(wv.z, xv.z, acc[2][2]);
        acc[2][3] = fmaf(wv.z, xv.w, acc[2][3]);
        acc[3][0] = fmaf(wv.w, xv.x, acc[3][0]);
        acc[3][1] = fmaf(wv.w, xv.y, acc[3][1]);
        acc[3][2] = fmaf(wv.w, xv.z, acc[3][2]);
        acc[3][3] = fmaf(wv.w, xv.w, acc[3][3]);
    }

    // ---- store y = acc + sY2 (STG.128, coalesced over p) ----
    #pragma unroll
    for (int tj = 0; tj < 4; ++tj) {
        const int t = 4 * j + tj;
        const float4 yv2 = *(const float4*)&sY2[IDX(t, 4 * i)];
        float* yrow = y + (((size_t)b * TLEN + t0 + t) * NH + hh) * PP;
        *(float4*)(yrow + 4 * i) = make_float4(acc[tj][0] + yv2.x,
                                               acc[tj][1] + yv2.y,
                                               acc[tj][2] + yv2.z,
                                               acc[tj][3] + yv2.w);
    }
}

extern "C" void kernel_launch(void* const* d_in, const int* in_sizes, int n_in,
                              void* d_out, int out_size) {
    const float* X     = (const float*)d_in[0];
    const float* delta = (const float*)d_in[1];
    const float* Bm    = (const float*)d_in[2];
    const float* Cm    = (const float*)d_in[3];
    const float* A_log = (const float*)d_in[4];

    float* y     = (float*)d_out;
    float* hlast = y + (size_t)BSZ * TLEN * NH * PP;

    const int k3_smem = 4 * CHL * LDS_ * (int)sizeof(float);  // 69632 B
    cudaFuncSetAttribute(k3_out, cudaFuncAttributeMaxDynamicSharedMemorySize, k3_smem);

    k1_state<<<BSZ * NH * NCH, 256>>>(X, delta, Bm, A_log);          // 1024 blocks
    k2_scan<<<(BSZ * NH * PP * NN) / 256, 256>>>(hlast);             // 512 blocks
    k3_out<<<BSZ * NH * NCH, 256, k3_smem>>>(X, delta, Bm, Cm, A_log, y);
}